// round 10
// baseline (speedup 1.0000x reference)
#include <cuda_runtime.h>
#include <cuda_bf16.h>

// PrototypeLoss: out = mean_i ||features[i] - prototypes[labels[i]]||^2
// N=131072, D=512, C=1000. Pure HBM-streaming reduction (~257 MB read).
// Single-kernel version: in-kernel label-dtype sniff + threadfence reduction
// (removes ~8us of sniff/finalize launch overhead measured in R8).
//
// inputs identified by element count (robust to ordering):
//   features f32 [N,D]   = 67108864 elems
//   labels   int [N]     = 131072 elems  (dtype sniffed on device: i32 vs i64)
//   protos   f32 [C,D]   = 512000 elems
// output: f32 [1,1]

#define N_ROWS 131072
#define N_CLASSES 1000
#define D_VEC  128          // D/4 float4 per row
#define GRID_BLOCKS (148 * 16)
#define BLOCK_THREADS 256
#define WARPS_TOTAL ((GRID_BLOCKS * BLOCK_THREADS) >> 5)

__device__ float    g_partials[GRID_BLOCKS];
__device__ unsigned g_done;     // zero-initialized at module load; reset by last block each run

__device__ __forceinline__ float row_dist_partial(const float4* __restrict__ f,
                                                  const float4* __restrict__ p,
                                                  int lane) {
    float acc = 0.0f;
    #pragma unroll
    for (int j = 0; j < 4; j++) {
        const int idx = lane + j * 32;
        float4 a = f[idx];
        float4 b = p[idx];
        float dx = a.x - b.x;
        float dy = a.y - b.y;
        float dz = a.z - b.z;
        float dw = a.w - b.w;
        acc = fmaf(dx, dx, acc);
        acc = fmaf(dy, dy, acc);
        acc = fmaf(dz, dz, acc);
        acc = fmaf(dw, dw, acc);
    }
    return acc;
}

__global__ __launch_bounds__(BLOCK_THREADS)
void proto_loss_kernel(const float4* __restrict__ feat,
                       const void* __restrict__ labels_raw,
                       const float4* __restrict__ protos,
                       float* __restrict__ out) {
    const int lane = threadIdx.x & 31;
    const int wid  = threadIdx.x >> 5;

    __shared__ int   s_is64;
    __shared__ float ssum[BLOCK_THREADS / 32];
    __shared__ int   s_last;

    // --- In-block label dtype sniff (warp 0): for int64 labels in [0,1000),
    // the odd 32-bit words of the first 64 entries are all zero. For int32
    // that needs 64 specific labels == 0 (p ~ 1e-192). Words 1..128 stay
    // within N*4 bytes for either dtype.
    if (wid == 0) {
        const unsigned* lw = (const unsigned*)labels_raw;
        unsigned w = lw[2 * lane + 1] | lw[2 * lane + 65];
        #pragma unroll
        for (int off = 16; off; off >>= 1)
            w |= __shfl_xor_sync(0xFFFFFFFFu, w, off);
        if (lane == 0) s_is64 = (w == 0u) ? 1 : 0;
    }
    __syncthreads();
    const int is64 = s_is64;
    const int*       l32 = (const int*)labels_raw;
    const long long* l64 = (const long long*)labels_raw;

    const int gwarp = (blockIdx.x * BLOCK_THREADS + threadIdx.x) >> 5;
    float acc = 0.0f;

    // Two rows in flight per warp iteration -> higher MLP to hide DRAM latency.
    for (int row = gwarp; row < N_ROWS; row += 2 * WARPS_TOTAL) {
        const int row0 = row;
        const int row1 = row + WARPS_TOTAL;

        int lbl0 = is64 ? (int)l64[row0] : l32[row0];
        lbl0 = (lbl0 < 0) ? 0 : (lbl0 >= N_CLASSES ? N_CLASSES - 1 : lbl0);
        const float4* f0 = feat   + (size_t)row0 * D_VEC;
        const float4* p0 = protos + (size_t)lbl0 * D_VEC;

        if (row1 < N_ROWS) {
            int lbl1 = is64 ? (int)l64[row1] : l32[row1];
            lbl1 = (lbl1 < 0) ? 0 : (lbl1 >= N_CLASSES ? N_CLASSES - 1 : lbl1);
            const float4* f1 = feat   + (size_t)row1 * D_VEC;
            const float4* p1 = protos + (size_t)lbl1 * D_VEC;
            acc += row_dist_partial(f0, p0, lane);
            acc += row_dist_partial(f1, p1, lane);
        } else {
            acc += row_dist_partial(f0, p0, lane);
        }
    }

    // warp reduce
    #pragma unroll
    for (int off = 16; off; off >>= 1)
        acc += __shfl_xor_sync(0xFFFFFFFFu, acc, off);
    if (lane == 0) ssum[wid] = acc;
    __syncthreads();

    // block reduce + publish partial; last block finishes
    if (wid == 0) {
        float v = (lane < (BLOCK_THREADS / 32)) ? ssum[lane] : 0.0f;
        #pragma unroll
        for (int off = 16; off; off >>= 1)
            v += __shfl_xor_sync(0xFFFFFFFFu, v, off);
        if (lane == 0) {
            g_partials[blockIdx.x] = v;
            __threadfence();
            unsigned ticket = atomicAdd(&g_done, 1u);
            s_last = (ticket == GRID_BLOCKS - 1) ? 1 : 0;
        }
    }
    __syncthreads();

    if (s_last) {
        // Last block: reduce all partials in double (fixed index order ->
        // deterministic), write output, reset counter for next graph replay.
        __threadfence();  // make all g_partials writes visible
        __shared__ double dsum[BLOCK_THREADS / 32];
        double d = 0.0;
        for (int i = threadIdx.x; i < GRID_BLOCKS; i += BLOCK_THREADS)
            d += (double)g_partials[i];
        #pragma unroll
        for (int off = 16; off; off >>= 1)
            d += __shfl_xor_sync(0xFFFFFFFFu, d, off);
        if (lane == 0) dsum[wid] = d;
        __syncthreads();
        if (wid == 0) {
            double t = (lane < (BLOCK_THREADS / 32)) ? dsum[lane] : 0.0;
            #pragma unroll
            for (int off = 16; off; off >>= 1)
                t += __shfl_xor_sync(0xFFFFFFFFu, t, off);
            if (lane == 0) {
                out[0] = (float)(t * (1.0 / (double)N_ROWS));
                g_done = 0u;   // reset for next replay
            }
        }
    }
}

extern "C" void kernel_launch(void* const* d_in, const int* in_sizes, int n_in,
                              void* d_out, int out_size) {
    // Identify inputs by element count (robust against metadata ordering).
    const float4* feat   = 0;
    const void*   labels = 0;
    const float4* protos = 0;
    for (int i = 0; i < n_in; i++) {
        if (in_sizes[i] == N_ROWS * 512)          feat   = (const float4*)d_in[i];
        else if (in_sizes[i] == N_CLASSES * 512)  protos = (const float4*)d_in[i];
        else                                      labels = d_in[i];
    }
    float* out = (float*)d_out;

    proto_loss_kernel<<<GRID_BLOCKS, BLOCK_THREADS>>>(feat, labels, protos, out);
}

// round 11
// speedup vs baseline: 1.1326x; 1.1326x over previous
#include <cuda_runtime.h>
#include <cuda_bf16.h>

// PrototypeLoss: out = mean_i ||features[i] - prototypes[labels[i]]||^2
// N=131072, D=512, C=1000. Pure HBM-streaming reduction (~257 MB read).
//
// Single kernel, single wave (148 SMs x 6 blocks), labels preloaded into
// lane registers and broadcast via shfl -> no label->gather dependency in
// the hot loop.
//
// inputs identified by element count:
//   features f32 [N,D] = 67108864, labels int [N] = 131072 (dtype sniffed),
//   protos f32 [C,D] = 512000.   output: f32 [1,1]

#define N_ROWS 131072
#define N_CLASSES 1000
#define D_VEC  128                 // D/4 float4 per row
#define GRID_BLOCKS (148 * 6)      // 888 blocks = exactly one wave at 6 blocks/SM
#define BLOCK_THREADS 256
#define WARPS_TOTAL ((GRID_BLOCKS * BLOCK_THREADS) >> 5)          // 7104
#define MAX_ITERS ((N_ROWS + WARPS_TOTAL - 1) / WARPS_TOTAL)      // 19

__device__ float    g_partials[GRID_BLOCKS];
__device__ unsigned g_done;   // zero-init at load; reset by last block each run

__device__ __forceinline__ float row_dist_partial(const float4* __restrict__ f,
                                                  const float4* __restrict__ p,
                                                  int lane) {
    float acc = 0.0f;
    #pragma unroll
    for (int j = 0; j < 4; j++) {
        const int idx = lane + j * 32;
        float4 a = f[idx];
        float4 b = p[idx];
        float dx = a.x - b.x;
        float dy = a.y - b.y;
        float dz = a.z - b.z;
        float dw = a.w - b.w;
        acc = fmaf(dx, dx, acc);
        acc = fmaf(dy, dy, acc);
        acc = fmaf(dz, dz, acc);
        acc = fmaf(dw, dw, acc);
    }
    return acc;
}

__global__ __launch_bounds__(BLOCK_THREADS, 6)
void proto_loss_kernel(const float4* __restrict__ feat,
                       const void* __restrict__ labels_raw,
                       const float4* __restrict__ protos,
                       float* __restrict__ out) {
    const int lane = threadIdx.x & 31;
    const int wid  = threadIdx.x >> 5;

    __shared__ int   s_is64;
    __shared__ float ssum[BLOCK_THREADS / 32];
    __shared__ int   s_last;

    // --- Label dtype sniff (warp 0): for int64 labels in [0,1000), the odd
    // 32-bit words of the first 64 entries are all zero. For int32 that needs
    // 64 specific labels == 0 (p ~ 1e-192). Words 1..128 stay within N*4
    // bytes for either dtype.
    if (wid == 0) {
        const unsigned* lw = (const unsigned*)labels_raw;
        unsigned w = lw[2 * lane + 1] | lw[2 * lane + 65];
        #pragma unroll
        for (int off = 16; off; off >>= 1)
            w |= __shfl_xor_sync(0xFFFFFFFFu, w, off);
        if (lane == 0) s_is64 = (w == 0u) ? 1 : 0;
    }
    __syncthreads();
    const int is64 = s_is64;
    const int*       l32 = (const int*)labels_raw;
    const long long* l64 = (const long long*)labels_raw;

    const int gwarp = (blockIdx.x * BLOCK_THREADS + threadIdx.x) >> 5;

    // --- Preload this warp's labels: lane k holds the label for iteration k.
    // Removes the label load (and its load->gather dependency) from the loop.
    int mylbl = 0;
    {
        const int myrow = gwarp + lane * WARPS_TOTAL;
        if (lane < MAX_ITERS && myrow < N_ROWS) {
            int l = is64 ? (int)l64[myrow] : l32[myrow];
            mylbl = (l < 0) ? 0 : (l >= N_CLASSES ? N_CLASSES - 1 : l);
        }
    }

    float acc = 0.0f;

    // Two rows per iteration; labels come from shfl (register), so all 16
    // float4 loads of an iteration can issue without waiting on anything.
    #pragma unroll
    for (int it = 0; it < MAX_ITERS; it += 2) {
        const int row0 = gwarp + it * WARPS_TOTAL;
        const int row1 = row0 + WARPS_TOTAL;
        const int lbl0 = __shfl_sync(0xFFFFFFFFu, mylbl, it);
        const int lbl1 = __shfl_sync(0xFFFFFFFFu, mylbl, it + 1);

        if (row1 < N_ROWS) {
            const float4* f0 = feat   + (size_t)row0 * D_VEC;
            const float4* p0 = protos + (size_t)lbl0 * D_VEC;
            const float4* f1 = feat   + (size_t)row1 * D_VEC;
            const float4* p1 = protos + (size_t)lbl1 * D_VEC;
            acc += row_dist_partial(f0, p0, lane);
            acc += row_dist_partial(f1, p1, lane);
        } else if (row0 < N_ROWS) {
            const float4* f0 = feat   + (size_t)row0 * D_VEC;
            const float4* p0 = protos + (size_t)lbl0 * D_VEC;
            acc += row_dist_partial(f0, p0, lane);
        }
    }

    // warp reduce
    #pragma unroll
    for (int off = 16; off; off >>= 1)
        acc += __shfl_xor_sync(0xFFFFFFFFu, acc, off);
    if (lane == 0) ssum[wid] = acc;
    __syncthreads();

    // block reduce + publish partial; last block to arrive finishes.
    if (wid == 0) {
        float v = (lane < (BLOCK_THREADS / 32)) ? ssum[lane] : 0.0f;
        #pragma unroll
        for (int off = 16; off; off >>= 1)
            v += __shfl_xor_sync(0xFFFFFFFFu, v, off);
        if (lane == 0) {
            g_partials[blockIdx.x] = v;
            __threadfence();
            unsigned ticket = atomicAdd(&g_done, 1u);
            s_last = (ticket == GRID_BLOCKS - 1) ? 1 : 0;
        }
    }
    __syncthreads();

    if (s_last) {
        __threadfence();  // all g_partials writes visible
        __shared__ double dsum[BLOCK_THREADS / 32];
        double d = 0.0;
        for (int i = threadIdx.x; i < GRID_BLOCKS; i += BLOCK_THREADS)
            d += (double)g_partials[i];
        #pragma unroll
        for (int off = 16; off; off >>= 1)
            d += __shfl_xor_sync(0xFFFFFFFFu, d, off);
        if (lane == 0) dsum[wid] = d;
        __syncthreads();
        if (wid == 0) {
            double t = (lane < (BLOCK_THREADS / 32)) ? dsum[lane] : 0.0;
            #pragma unroll
            for (int off = 16; off; off >>= 1)
                t += __shfl_xor_sync(0xFFFFFFFFu, t, off);
            if (lane == 0) {
                out[0] = (float)(t * (1.0 / (double)N_ROWS));
                g_done = 0u;   // reset for next graph replay
            }
        }
    }
}

extern "C" void kernel_launch(void* const* d_in, const int* in_sizes, int n_in,
                              void* d_out, int out_size) {
    const float4* feat   = 0;
    const void*   labels = 0;
    const float4* protos = 0;
    for (int i = 0; i < n_in; i++) {
        if (in_sizes[i] == N_ROWS * 512)          feat   = (const float4*)d_in[i];
        else if (in_sizes[i] == N_CLASSES * 512)  protos = (const float4*)d_in[i];
        else                                      labels = d_in[i];
    }
    float* out = (float*)d_out;

    proto_loss_kernel<<<GRID_BLOCKS, BLOCK_THREADS>>>(feat, labels, protos, out);
}